// round 1
// baseline (speedup 1.0000x reference)
#include <cuda_runtime.h>
#include <math.h>

// ---------------------------------------------------------------------------
// Fused MLP:  x[65536,365] -> L1(512,relu) -> L2(256,relu) -> L3(128,relu)
//             row-stats(x)[6] @ Ws + bs -> [32]
//             concat[160] -> C1(64,relu) -> C2(32,relu) -> C3(1) -> sigmoid
// One block = 64 rows, everything stays in SMEM. Weights stream from L2.
// fp32 math via packed fma.rn.f32x2 (2 FMA/instr on sm_103a fp32 pipe).
// ---------------------------------------------------------------------------

#define TM 64
#define NTHREADS 256
#define D_IN 365

// smem layout in floats:
//   Xs   [64*365]  : x tile; later h2 (64x256); later c1out (64x64)
//   Hs   [64*512]  : h1; later comb (64x160); later c2out (64x32)
//   Sraw [64*8]    : raw row stats (mu,sigma,min,max,skew,kurt)
#define XS_OFF   0
#define HS_OFF   (TM * D_IN)            // 23360
#define SR_OFF   (HS_OFF + TM * 512)    // 56128
#define SMEM_FLOATS (SR_OFF + TM * 8)   // 56640 -> 226560 bytes

__device__ __forceinline__ unsigned long long pack2(float lo, float hi) {
    unsigned long long r;
    asm("mov.b64 %0, {%1, %2};" : "=l"(r) : "f"(lo), "f"(hi));
    return r;
}
__device__ __forceinline__ void unpack2(unsigned long long v, float& lo, float& hi) {
    asm("mov.b64 {%0, %1}, %2;" : "=f"(lo), "=f"(hi) : "l"(v));
}
__device__ __forceinline__ unsigned long long fma2(unsigned long long a,
                                                   unsigned long long b,
                                                   unsigned long long c) {
    unsigned long long d;
    asm("fma.rn.f32x2 %0, %1, %2, %3;" : "=l"(d) : "l"(a), "l"(b), "l"(c));
    return d;
}

// Packed-f32x2 GEMM phase over a 64-row tile.
// Thread map: tc = tid&31 (column lane), tr = tid>>5 (row octet).
// Thread computes RM rows x U cols; cols are tc + 32*u, packed in pairs
// (tc+64*u2, tc+64*u2+32). A is smem [64 x lda]; W is gmem [K x N] row-major.
template <int RM, int U, bool RELU>
__device__ __forceinline__ void gemm_packed(const float* __restrict__ As, int lda,
                                            const float* __restrict__ W,
                                            const float* __restrict__ bias,
                                            int N, int K,
                                            float* __restrict__ Cs, int ldc) {
    constexpr int U2 = U / 2;
    const int tc = threadIdx.x & 31;
    const int tr = threadIdx.x >> 5;
    const float* Arow = As + tr * RM * lda;

    unsigned long long acc[RM][U2];
#pragma unroll
    for (int i = 0; i < RM; i++)
#pragma unroll
        for (int u = 0; u < U2; u++) acc[i][u] = 0ULL;

    float wbuf[2][U];
    {
        const float* W0 = W + tc;
#pragma unroll
        for (int u = 0; u < U; u++) wbuf[0][u] = W0[32 * u];
    }

    for (int k = 0; k < K; k++) {
        const int cur = k & 1;
        if (k + 1 < K) {
            const float* Wn = W + (size_t)(k + 1) * N + tc;
#pragma unroll
            for (int u = 0; u < U; u++) wbuf[cur ^ 1][u] = Wn[32 * u];
        }
        unsigned long long wp[U2];
#pragma unroll
        for (int u = 0; u < U2; u++)
            wp[u] = pack2(wbuf[cur][2 * u], wbuf[cur][2 * u + 1]);
#pragma unroll
        for (int i = 0; i < RM; i++) {
            float xv = Arow[i * lda + k];  // warp-uniform -> LDS broadcast
            unsigned long long xp = pack2(xv, xv);
#pragma unroll
            for (int u = 0; u < U2; u++) acc[i][u] = fma2(xp, wp[u], acc[i][u]);
        }
    }

#pragma unroll
    for (int u = 0; u < U2; u++) {
        float b0 = bias[tc + 64 * u];
        float b1 = bias[tc + 64 * u + 32];
#pragma unroll
        for (int i = 0; i < RM; i++) {
            float lo, hi;
            unpack2(acc[i][u], lo, hi);
            lo += b0; hi += b1;
            if (RELU) { lo = fmaxf(lo, 0.f); hi = fmaxf(hi, 0.f); }
            float* crow = Cs + (tr * RM + i) * ldc + tc + 64 * u;
            crow[0]  = lo;
            crow[32] = hi;
        }
    }
}

// Scalar GEMM for the small head layers (N=64 / N=32).
template <int RM, int U, bool RELU>
__device__ __forceinline__ void gemm_scalar(const float* __restrict__ As, int lda,
                                            const float* __restrict__ W,
                                            const float* __restrict__ bias,
                                            int N, int K,
                                            float* __restrict__ Cs, int ldc) {
    const int tc = threadIdx.x & 31;
    const int tr = threadIdx.x >> 5;
    const float* Arow = As + tr * RM * lda;

    float acc[RM][U];
#pragma unroll
    for (int i = 0; i < RM; i++)
#pragma unroll
        for (int u = 0; u < U; u++) acc[i][u] = 0.f;

    for (int k = 0; k < K; k++) {
        float wv[U];
        const float* Wk = W + (size_t)k * N + tc;
#pragma unroll
        for (int u = 0; u < U; u++) wv[u] = Wk[32 * u];
#pragma unroll
        for (int i = 0; i < RM; i++) {
            float xv = Arow[i * lda + k];
#pragma unroll
            for (int u = 0; u < U; u++) acc[i][u] += xv * wv[u];
        }
    }
#pragma unroll
    for (int u = 0; u < U; u++) {
        float b = bias[tc + 32 * u];
#pragma unroll
        for (int i = 0; i < RM; i++) {
            float v = acc[i][u] + b;
            if (RELU) v = fmaxf(v, 0.f);
            Cs[(tr * RM + i) * ldc + tc + 32 * u] = v;
        }
    }
}

__global__ __launch_bounds__(NTHREADS, 1)
void mlp_fused_kernel(const float* __restrict__ x,
                      const float* __restrict__ W1, const float* __restrict__ b1,
                      const float* __restrict__ W2, const float* __restrict__ b2,
                      const float* __restrict__ W3, const float* __restrict__ b3,
                      const float* __restrict__ Ws, const float* __restrict__ bs,
                      const float* __restrict__ Wc1, const float* __restrict__ bc1,
                      const float* __restrict__ Wc2, const float* __restrict__ bc2,
                      const float* __restrict__ Wc3, const float* __restrict__ bc3,
                      float* __restrict__ out) {
    extern __shared__ float sm[];
    float* Xs = sm + XS_OFF;
    float* Hs = sm + HS_OFF;
    float* Sraw = sm + SR_OFF;

    const int row0 = blockIdx.x * TM;

    // ---- P0: load x tile (contiguous, coalesced) ----
    const float* xg = x + (size_t)row0 * D_IN;
    for (int idx = threadIdx.x; idx < TM * D_IN; idx += NTHREADS)
        Xs[idx] = xg[idx];
    __syncthreads();

    // ---- P1: raw row stats (one row per thread, threads 0..63) ----
    if (threadIdx.x < TM) {
        const float* xr = Xs + threadIdx.x * D_IN;
        float s = 0.f, mn = xr[0], mx = xr[0];
        for (int k = 0; k < D_IN; k++) {
            float v = xr[k];
            s += v;
            mn = fminf(mn, v);
            mx = fmaxf(mx, v);
        }
        float mu = s * (1.0f / D_IN);
        float s2 = 0.f, s3 = 0.f, s4 = 0.f;
        for (int k = 0; k < D_IN; k++) {
            float c = xr[k] - mu;
            float c2 = c * c;
            s2 += c2;
            s3 += c2 * c;
            s4 += c2 * c2;
        }
        float var1 = s2 * (1.0f / (D_IN - 1));
        float sig = sqrtf(var1);
        float m3 = s3 * (1.0f / D_IN);
        float m4 = s4 * (1.0f / D_IN);
        float sig2 = sig * sig;
        float skew = m3 / (sig * sig2 + 1e-8f);
        float kurt = m4 / (sig2 * sig2 + 1e-8f);
        float* sr = Sraw + threadIdx.x * 8;
        sr[0] = mu; sr[1] = sig; sr[2] = mn; sr[3] = mx; sr[4] = skew; sr[5] = kurt;
    }
    __syncthreads();

    // ---- P2: L1  [64,365] @ [365,512] -> Hs (h1, ldc=512) ----
    gemm_packed<8, 16, true>(Xs, D_IN, W1, b1, 512, D_IN, Hs, 512);
    __syncthreads();

    // ---- P3: L2  h1 @ [512,256] -> Xs region (h2, ldc=256) ----
    gemm_packed<8, 8, true>(Hs, 512, W2, b2, 256, 512, Xs, 256);
    __syncthreads();

    // ---- P4: L3  h2 @ [256,128] -> Hs as comb cols [0,128), ldc=160 ----
    gemm_packed<8, 4, true>(Xs, 256, W3, b3, 128, 256, Hs, 160);

    // ---- P5: stats branch: Sraw[6] @ Ws[6,32] + bs -> comb cols [128,160) ----
    // (disjoint smem region from P4's writes; Sraw stable since P1 sync)
    for (int o = threadIdx.x; o < TM * 32; o += NTHREADS) {
        int r = o >> 5, j = o & 31;
        const float* sr = Sraw + r * 8;
        float a = bs[j];
#pragma unroll
        for (int k = 0; k < 6; k++) a += sr[k] * Ws[k * 32 + j];
        Hs[r * 160 + 128 + j] = a;
    }
    __syncthreads();

    // ---- P6: C1  comb[64,160] @ [160,64] -> Xs (c1out, ldc=64) ----
    gemm_scalar<8, 2, true>(Hs, 160, Wc1, bc1, 64, 160, Xs, 64);
    __syncthreads();

    // ---- P7: C2  c1out @ [64,32] -> Hs (c2out, ldc=32) ----
    gemm_scalar<8, 1, true>(Xs, 64, Wc2, bc2, 32, 64, Hs, 32);
    __syncthreads();

    // ---- P8: C3 + sigmoid ----
    if (threadIdx.x < TM) {
        const float* cr = Hs + threadIdx.x * 32;
        float z = bc3[0];
#pragma unroll
        for (int k = 0; k < 32; k++) z += cr[k] * Wc3[k];
        out[row0 + threadIdx.x] = 1.0f / (1.0f + expf(-z));
    }
}

extern "C" void kernel_launch(void* const* d_in, const int* in_sizes, int n_in,
                              void* d_out, int out_size) {
    const float* x   = (const float*)d_in[0];
    const float* W1  = (const float*)d_in[1];
    const float* b1  = (const float*)d_in[2];
    const float* W2  = (const float*)d_in[3];
    const float* b2  = (const float*)d_in[4];
    const float* W3  = (const float*)d_in[5];
    const float* b3  = (const float*)d_in[6];
    const float* Ws  = (const float*)d_in[7];
    const float* bs  = (const float*)d_in[8];
    const float* Wc1 = (const float*)d_in[9];
    const float* bc1 = (const float*)d_in[10];
    const float* Wc2 = (const float*)d_in[11];
    const float* bc2 = (const float*)d_in[12];
    const float* Wc3 = (const float*)d_in[13];
    const float* bc3 = (const float*)d_in[14];
    float* out = (float*)d_out;

    const int B = in_sizes[0] / D_IN;         // 65536
    const int nblocks = B / TM;               // 1024
    const size_t smem = SMEM_FLOATS * sizeof(float);  // 226560 B

    static bool attr_set = false;
    if (!attr_set) {
        cudaFuncSetAttribute(mlp_fused_kernel,
                             cudaFuncAttributeMaxDynamicSharedMemorySize,
                             (int)smem);
        attr_set = true;
    }

    mlp_fused_kernel<<<nblocks, NTHREADS, smem>>>(
        x, W1, b1, W2, b2, W3, b3, Ws, bs, Wc1, bc1, Wc2, bc2, Wc3, bc3, out);
}

// round 2
// speedup vs baseline: 2.0973x; 2.0973x over previous
#include <cuda_runtime.h>
#include <math.h>

// ---------------------------------------------------------------------------
// Fused MLP:  x[65536,365] -> L1(512,relu) -> L2(256,relu) -> L3(128,relu)
//             row-stats(x)[6] @ Ws + bs -> [32]
//             concat[160] -> C1(64,relu) -> C2(32,relu) -> C3(1) -> sigmoid
// TM=32 rows/block, 113KB smem -> 2 CTAs/SM (16 warps). Packed fma.rn.f32x2
// with LDG.128 weight loads that land directly as packed operand pairs.
// ---------------------------------------------------------------------------

#define TM 32
#define NTHREADS 256
#define D_IN 365

// smem layout in floats:
//   Xs   [32*365]  : x tile; later h2 (32x256); later c1out (32x64)
//   Hs   [32*512]  : h1; later comb (32x160); later c2out (32x32)
//   Sraw [32*8]    : raw row stats
#define XS_OFF   0
#define HS_OFF   (TM * D_IN)            // 11680
#define SR_OFF   (HS_OFF + TM * 512)    // 28064
#define SMEM_FLOATS (SR_OFF + TM * 8)   // 28320 floats = 113280 bytes

__device__ __forceinline__ unsigned long long pack2(float lo, float hi) {
    unsigned long long r;
    asm("mov.b64 %0, {%1, %2};" : "=l"(r) : "f"(lo), "f"(hi));
    return r;
}
__device__ __forceinline__ void unpack2(unsigned long long v, float& lo, float& hi) {
    asm("mov.b64 {%0, %1}, %2;" : "=f"(lo), "=f"(hi) : "l"(v));
}
__device__ __forceinline__ unsigned long long fma2(unsigned long long a,
                                                   unsigned long long b,
                                                   unsigned long long c) {
    unsigned long long d;
    asm("fma.rn.f32x2 %0, %1, %2, %3;" : "=l"(d) : "l"(a), "l"(b), "l"(c));
    return d;
}

// Vectorized packed-f32x2 GEMM over the 32-row tile.
// tc = tid&31 owns 4 contiguous columns per u-slice: cols [tc*4+128u, +4).
// tr = tid>>5 owns RM=4 rows. Weights loaded as ulonglong2 (LDG.128) whose
// two u64 halves are already packed f32x2 operands (no mov overhead).
template <int RM, int U4, bool RELU>
__device__ __forceinline__ void gemm_vec(const float* __restrict__ As, int lda,
                                         const float* __restrict__ W,
                                         const float* __restrict__ bias,
                                         int N, int K,
                                         float* __restrict__ Cs, int ldc) {
    const int tc = threadIdx.x & 31;
    const int tr = threadIdx.x >> 5;
    const int colb = tc * 4;
    const float* Arow = As + tr * RM * lda;

    unsigned long long acc[RM][U4][2];
#pragma unroll
    for (int i = 0; i < RM; i++)
#pragma unroll
        for (int u = 0; u < U4; u++) { acc[i][u][0] = 0ULL; acc[i][u][1] = 0ULL; }

    ulonglong2 wb[2][U4];
#pragma unroll
    for (int u = 0; u < U4; u++)
        wb[0][u] = *(const ulonglong2*)(W + colb + 128 * u);

    for (int k = 0; k < K; k++) {
        const int cur = k & 1;
        if (k + 1 < K) {
            const float* Wn = W + (size_t)(k + 1) * N + colb;
#pragma unroll
            for (int u = 0; u < U4; u++)
                wb[cur ^ 1][u] = *(const ulonglong2*)(Wn + 128 * u);
        }
#pragma unroll
        for (int i = 0; i < RM; i++) {
            float xv = Arow[i * lda + k];   // warp-uniform LDS broadcast
            unsigned long long xp = pack2(xv, xv);
#pragma unroll
            for (int u = 0; u < U4; u++) {
                acc[i][u][0] = fma2(xp, wb[cur][u].x, acc[i][u][0]);
                acc[i][u][1] = fma2(xp, wb[cur][u].y, acc[i][u][1]);
            }
        }
    }

#pragma unroll
    for (int u = 0; u < U4; u++) {
        float4 b4 = *(const float4*)(bias + colb + 128 * u);
#pragma unroll
        for (int i = 0; i < RM; i++) {
            float c0, c1, c2, c3;
            unpack2(acc[i][u][0], c0, c1);
            unpack2(acc[i][u][1], c2, c3);
            c0 += b4.x; c1 += b4.y; c2 += b4.z; c3 += b4.w;
            if (RELU) {
                c0 = fmaxf(c0, 0.f); c1 = fmaxf(c1, 0.f);
                c2 = fmaxf(c2, 0.f); c3 = fmaxf(c3, 0.f);
            }
            float4 o = make_float4(c0, c1, c2, c3);
            *(float4*)(Cs + (tr * RM + i) * ldc + colb + 128 * u) = o;
        }
    }
}

// Scalar GEMM for the small head layers (N=64 / N=32), cols tc + 32u.
template <int RM, int U, bool RELU>
__device__ __forceinline__ void gemm_scalar(const float* __restrict__ As, int lda,
                                            const float* __restrict__ W,
                                            const float* __restrict__ bias,
                                            int N, int K,
                                            float* __restrict__ Cs, int ldc) {
    const int tc = threadIdx.x & 31;
    const int tr = threadIdx.x >> 5;
    const float* Arow = As + tr * RM * lda;

    float acc[RM][U];
#pragma unroll
    for (int i = 0; i < RM; i++)
#pragma unroll
        for (int u = 0; u < U; u++) acc[i][u] = 0.f;

    for (int k = 0; k < K; k++) {
        float wv[U];
        const float* Wk = W + (size_t)k * N + tc;
#pragma unroll
        for (int u = 0; u < U; u++) wv[u] = Wk[32 * u];
#pragma unroll
        for (int i = 0; i < RM; i++) {
            float xv = Arow[i * lda + k];
#pragma unroll
            for (int u = 0; u < U; u++) acc[i][u] += xv * wv[u];
        }
    }
#pragma unroll
    for (int u = 0; u < U; u++) {
        float b = bias[tc + 32 * u];
#pragma unroll
        for (int i = 0; i < RM; i++) {
            float v = acc[i][u] + b;
            if (RELU) v = fmaxf(v, 0.f);
            Cs[(tr * RM + i) * ldc + tc + 32 * u] = v;
        }
    }
}

__global__ __launch_bounds__(NTHREADS, 2)
void mlp_fused_kernel(const float* __restrict__ x,
                      const float* __restrict__ W1, const float* __restrict__ b1,
                      const float* __restrict__ W2, const float* __restrict__ b2,
                      const float* __restrict__ W3, const float* __restrict__ b3,
                      const float* __restrict__ Ws, const float* __restrict__ bs,
                      const float* __restrict__ Wc1, const float* __restrict__ bc1,
                      const float* __restrict__ Wc2, const float* __restrict__ bc2,
                      const float* __restrict__ Wc3, const float* __restrict__ bc3,
                      float* __restrict__ out) {
    extern __shared__ float sm[];
    float* Xs = sm + XS_OFF;
    float* Hs = sm + HS_OFF;
    float* Sraw = sm + SR_OFF;

    const int row0 = blockIdx.x * TM;

    // ---- P0: load x tile (32*365 = 11680 floats, 16B-aligned chunk) ----
    {
        const float4* xg4 = (const float4*)(x + (size_t)row0 * D_IN);
        float4* Xs4 = (float4*)Xs;
        for (int idx = threadIdx.x; idx < TM * D_IN / 4; idx += NTHREADS)
            Xs4[idx] = xg4[idx];
    }
    __syncthreads();

    // ---- P1: row stats, 8 lanes per row (width-8 shfl reduction) ----
    {
        const int r = threadIdx.x >> 3;
        const int sub = threadIdx.x & 7;
        const float* xr = Xs + r * D_IN;

        float s = 0.f, mn = 3.4e38f, mx = -3.4e38f;
        for (int k = sub; k < D_IN; k += 8) {
            float v = xr[k];
            s += v; mn = fminf(mn, v); mx = fmaxf(mx, v);
        }
#pragma unroll
        for (int o = 4; o > 0; o >>= 1) {
            s  += __shfl_xor_sync(0xffffffffu, s, o, 8);
            mn = fminf(mn, __shfl_xor_sync(0xffffffffu, mn, o, 8));
            mx = fmaxf(mx, __shfl_xor_sync(0xffffffffu, mx, o, 8));
        }
        float mu = s * (1.0f / D_IN);
        float s2 = 0.f, s3 = 0.f, s4 = 0.f;
        for (int k = sub; k < D_IN; k += 8) {
            float c = xr[k] - mu;
            float c2 = c * c;
            s2 += c2; s3 += c2 * c; s4 += c2 * c2;
        }
#pragma unroll
        for (int o = 4; o > 0; o >>= 1) {
            s2 += __shfl_xor_sync(0xffffffffu, s2, o, 8);
            s3 += __shfl_xor_sync(0xffffffffu, s3, o, 8);
            s4 += __shfl_xor_sync(0xffffffffu, s4, o, 8);
        }
        if (sub == 0) {
            float var1 = s2 * (1.0f / (D_IN - 1));
            float sig = sqrtf(var1);
            float m3 = s3 * (1.0f / D_IN);
            float m4 = s4 * (1.0f / D_IN);
            float sig2 = sig * sig;
            float skew = m3 / (sig * sig2 + 1e-8f);
            float kurt = m4 / (sig2 * sig2 + 1e-8f);
            float* sr = Sraw + r * 8;
            sr[0] = mu; sr[1] = sig; sr[2] = mn; sr[3] = mx;
            sr[4] = skew; sr[5] = kurt;
        }
    }
    __syncthreads();

    // ---- P2: L1  [32,365] @ [365,512] -> Hs (h1, ldc=512) ----
    gemm_vec<4, 4, true>(Xs, D_IN, W1, b1, 512, D_IN, Hs, 512);
    __syncthreads();

    // ---- P3: L2  h1 @ [512,256] -> Xs region (h2, ldc=256) ----
    gemm_vec<4, 2, true>(Hs, 512, W2, b2, 256, 512, Xs, 256);
    __syncthreads();

    // ---- P4: L3  h2 @ [256,128] -> Hs comb cols [0,128), ldc=160 ----
    gemm_vec<4, 1, true>(Xs, 256, W3, b3, 128, 256, Hs, 160);

    // ---- P5: stats linear -> comb cols [128,160) (disjoint from P4) ----
    for (int o = threadIdx.x; o < TM * 32; o += NTHREADS) {
        int r = o >> 5, j = o & 31;
        const float* sr = Sraw + r * 8;
        float a = bs[j];
#pragma unroll
        for (int k = 0; k < 6; k++) a += sr[k] * Ws[k * 32 + j];
        Hs[r * 160 + 128 + j] = a;
    }
    __syncthreads();

    // ---- P6: C1  comb[32,160] @ [160,64] -> Xs (c1out, ldc=64) ----
    gemm_scalar<4, 2, true>(Hs, 160, Wc1, bc1, 64, 160, Xs, 64);
    __syncthreads();

    // ---- P7: C2  c1out @ [64,32] -> Hs (c2out, ldc=32) ----
    gemm_scalar<4, 1, true>(Xs, 64, Wc2, bc2, 32, 64, Hs, 32);
    __syncthreads();

    // ---- P8: C3 + sigmoid ----
    if (threadIdx.x < TM) {
        const float* cr = Hs + threadIdx.x * 32;
        float z = bc3[0];
#pragma unroll
        for (int k = 0; k < 32; k++) z += cr[k] * Wc3[k];
        out[row0 + threadIdx.x] = 1.0f / (1.0f + expf(-z));
    }
}

extern "C" void kernel_launch(void* const* d_in, const int* in_sizes, int n_in,
                              void* d_out, int out_size) {
    const float* x   = (const float*)d_in[0];
    const float* W1  = (const float*)d_in[1];
    const float* b1  = (const float*)d_in[2];
    const float* W2  = (const float*)d_in[3];
    const float* b2  = (const float*)d_in[4];
    const float* W3  = (const float*)d_in[5];
    const float* b3  = (const float*)d_in[6];
    const float* Ws  = (const float*)d_in[7];
    const float* bs  = (const float*)d_in[8];
    const float* Wc1 = (const float*)d_in[9];
    const float* bc1 = (const float*)d_in[10];
    const float* Wc2 = (const float*)d_in[11];
    const float* bc2 = (const float*)d_in[12];
    const float* Wc3 = (const float*)d_in[13];
    const float* bc3 = (const float*)d_in[14];
    float* out = (float*)d_out;

    const int B = in_sizes[0] / D_IN;         // 65536
    const int nblocks = B / TM;               // 2048
    const size_t smem = SMEM_FLOATS * sizeof(float);  // 113280 B

    static bool attr_set = false;
    if (!attr_set) {
        cudaFuncSetAttribute(mlp_fused_kernel,
                             cudaFuncAttributeMaxDynamicSharedMemorySize,
                             (int)smem);
        attr_set = true;
    }

    mlp_fused_kernel<<<nblocks, NTHREADS, smem>>>(
        x, W1, b1, W2, b2, W3, b3, Ws, bs, Wc1, bc1, Wc2, bc2, Wc3, bc3, out);
}

// round 4
// speedup vs baseline: 3.9350x; 1.8762x over previous
#include <cuda_runtime.h>
#include <cuda_bf16.h>
#include <math.h>
#include <cstdint>

// ===========================================================================
// Multi-kernel fused MLP using mma.sync (HMMA bf16, hi/lo split = fp32-grade):
//   prep_x : x fp32 -> x_hi/x_lo bf16 [65536,384] (+ row stats)
//   prep_w : W1/W2/W3 -> transposed [N,Kpad] bf16 hi/lo
//   gemm<1>: h1 = relu(x@W1+b1)   [65536,512]  (bf16 hi/lo out)
//   gemm<2>: h2 = relu(h1@W2+b2)  [65536,256]  (bf16 hi/lo out)
//   gemm<3>: h3 = relu(h2@W3+b3)  [65536,128]  (fp32 out)
//   head   : stats@Ws -> concat -> C1,C2,C3 -> sigmoid
// GEMM: block tile 64(M)x256(N) [128 for L3], K-chunk 64, warp tile 16x128,
// ldmatrix.x4 + mma.m16n8k16; D += Ah*Bh + Ah*Bl + Al*Bh.
// ===========================================================================

#define MTOT 65536

// ---------------- device scratch -------------------------------------------
__device__ __nv_bfloat16 g_xh[(size_t)MTOT * 384];
__device__ __nv_bfloat16 g_xl[(size_t)MTOT * 384];
__device__ __nv_bfloat16 g_w1h[512 * 384], g_w1l[512 * 384];
__device__ __nv_bfloat16 g_w2h[256 * 512], g_w2l[256 * 512];
__device__ __nv_bfloat16 g_w3h[128 * 256], g_w3l[128 * 256];
__device__ __nv_bfloat16 g_h1h[(size_t)MTOT * 512], g_h1l[(size_t)MTOT * 512];
__device__ __nv_bfloat16 g_h2h[(size_t)MTOT * 256], g_h2l[(size_t)MTOT * 256];
__device__ float g_h3[(size_t)MTOT * 128];
__device__ float g_stats[(size_t)MTOT * 8];

// ---------------- helpers --------------------------------------------------
__device__ __forceinline__ uint32_t smem_to_u32(const void* p) {
    uint32_t a;
    asm("{ .reg .u64 t; cvta.to.shared.u64 t, %1; cvt.u32.u64 %0, t; }"
        : "=r"(a) : "l"(p));
    return a;
}
__device__ __forceinline__ void ldsm4(uint32_t* r, uint32_t addr) {
    asm volatile("ldmatrix.sync.aligned.m8n8.x4.shared.b16 {%0,%1,%2,%3}, [%4];"
        : "=r"(r[0]), "=r"(r[1]), "=r"(r[2]), "=r"(r[3]) : "r"(addr));
}
__device__ __forceinline__ void mma16816(float* c, const uint32_t* a,
                                         const uint32_t* b) {
    asm volatile(
        "mma.sync.aligned.m16n8k16.row.col.f32.bf16.bf16.f32 "
        "{%0,%1,%2,%3}, {%4,%5,%6,%7}, {%8,%9}, {%0,%1,%2,%3};"
        : "+f"(c[0]), "+f"(c[1]), "+f"(c[2]), "+f"(c[3])
        : "r"(a[0]), "r"(a[1]), "r"(a[2]), "r"(a[3]), "r"(b[0]), "r"(b[1]));
}
__device__ __forceinline__ void split_bf16(float v, __nv_bfloat16& hi,
                                           __nv_bfloat16& lo) {
    hi = __float2bfloat16(v);
    lo = __float2bfloat16(v - __bfloat162float(hi));
}
__device__ __forceinline__ uint32_t pack_bf16x2(__nv_bfloat16 a, __nv_bfloat16 b) {
    __nv_bfloat162 t; t.x = a; t.y = b;
    return *(uint32_t*)&t;
}

// ---------------- prep_x: split x + row stats ------------------------------
__global__ __launch_bounds__(256)
void prep_x_kernel(const float* __restrict__ x) {
    const int warp = threadIdx.x >> 5, lane = threadIdx.x & 31;
    const int r = blockIdx.x * 8 + warp;
    const float* xr = x + (size_t)r * 365;

    float v[12];
    float s = 0.f, mn = 3.4e38f, mx = -3.4e38f;
#pragma unroll
    for (int i = 0; i < 12; i++) {
        int k = lane + 32 * i;
        bool ok = k < 365;
        v[i] = ok ? xr[k] : 0.f;
        if (ok) { s += v[i]; mn = fminf(mn, v[i]); mx = fmaxf(mx, v[i]); }
    }
#pragma unroll
    for (int o = 16; o; o >>= 1) {
        s += __shfl_xor_sync(0xffffffffu, s, o);
        mn = fminf(mn, __shfl_xor_sync(0xffffffffu, mn, o));
        mx = fmaxf(mx, __shfl_xor_sync(0xffffffffu, mx, o));
    }
    const float mu = s * (1.0f / 365.0f);
    float s2 = 0.f, s3 = 0.f, s4 = 0.f;
#pragma unroll
    for (int i = 0; i < 12; i++) {
        int k = lane + 32 * i;
        if (k < 365) {
            float c = v[i] - mu, c2 = c * c;
            s2 += c2; s3 += c2 * c; s4 += c2 * c2;
        }
    }
#pragma unroll
    for (int o = 16; o; o >>= 1) {
        s2 += __shfl_xor_sync(0xffffffffu, s2, o);
        s3 += __shfl_xor_sync(0xffffffffu, s3, o);
        s4 += __shfl_xor_sync(0xffffffffu, s4, o);
    }
    if (lane == 0) {
        float var1 = s2 * (1.0f / 364.0f);
        float sig = sqrtf(var1);
        float m3 = s3 * (1.0f / 365.0f);
        float m4 = s4 * (1.0f / 365.0f);
        float sig2 = sig * sig;
        float* st = g_stats + (size_t)r * 8;
        st[0] = mu; st[1] = sig; st[2] = mn; st[3] = mx;
        st[4] = m3 / (sig * sig2 + 1e-8f);
        st[5] = m4 / (sig2 * sig2 + 1e-8f);
    }
#pragma unroll
    for (int i = 0; i < 12; i++) {
        int k = lane + 32 * i;
        float val = (k < 365) ? v[i] : 0.f;
        __nv_bfloat16 hi, lo;
        split_bf16(val, hi, lo);
        g_xh[(size_t)r * 384 + k] = hi;
        g_xl[(size_t)r * 384 + k] = lo;
    }
}

// ---------------- prep_w: transpose + split weights ------------------------
#define W1T_ELEMS (512 * 384)
#define W2T_ELEMS (256 * 512)
#define W3T_ELEMS (128 * 256)
#define WT_TOTAL  (W1T_ELEMS + W2T_ELEMS + W3T_ELEMS)

__global__ __launch_bounds__(256)
void prep_w_kernel(const float* __restrict__ W1, const float* __restrict__ W2,
                   const float* __restrict__ W3) {
    int idx = blockIdx.x * 256 + threadIdx.x;
    if (idx >= WT_TOTAL) return;
    float v; __nv_bfloat16 hi, lo;
    if (idx < W1T_ELEMS) {
        int n = idx / 384, k = idx % 384;
        v = (k < 365) ? W1[(size_t)k * 512 + n] : 0.f;
        split_bf16(v, hi, lo);
        g_w1h[idx] = hi; g_w1l[idx] = lo;
    } else if (idx < W1T_ELEMS + W2T_ELEMS) {
        int j = idx - W1T_ELEMS;
        int n = j / 512, k = j % 512;
        v = W2[(size_t)k * 256 + n];
        split_bf16(v, hi, lo);
        g_w2h[j] = hi; g_w2l[j] = lo;
    } else {
        int j = idx - W1T_ELEMS - W2T_ELEMS;
        int n = j / 256, k = j % 256;
        v = W3[(size_t)k * 128 + n];
        split_bf16(v, hi, lo);
        g_w3h[j] = hi; g_w3l[j] = lo;
    }
}

// ---------------- HMMA GEMM (per layer) ------------------------------------
// D[m,n] = sum_k A[m,k] * B[n,k]; smem padded stride 144B (72 bf16).
template <int LAYER>
__global__ __launch_bounds__(256, 2)
void gemm_hmma_kernel(const float* __restrict__ bias) {
    constexpr int KPAD  = (LAYER == 1) ? 384 : (LAYER == 2) ? 512 : 256;
    constexpr int BLK_N = (LAYER == 3) ? 128 : 256;
    constexpr int OUTLD = (LAYER == 1) ? 512 : (LAYER == 2) ? 256 : 128;
    constexpr int KB    = KPAD / 64;
    constexpr int WN    = BLK_N / 2;       // per-warp N span (128 or 64)
    constexpr int NT    = WN / 8;          // n-tiles per warp (16 or 8)
    constexpr bool SPLIT = (LAYER != 3);
    constexpr int LDSB  = 144;             // bytes per smem row (64 bf16 + pad)

    const __nv_bfloat16* Ah_g = (LAYER == 1) ? g_xh  : (LAYER == 2) ? g_h1h : g_h2h;
    const __nv_bfloat16* Al_g = (LAYER == 1) ? g_xl  : (LAYER == 2) ? g_h1l : g_h2l;
    const __nv_bfloat16* Bh_g = (LAYER == 1) ? g_w1h : (LAYER == 2) ? g_w2h : g_w3h;
    const __nv_bfloat16* Bl_g = (LAYER == 1) ? g_w1l : (LAYER == 2) ? g_w2l : g_w3l;
    __nv_bfloat16* Oh = (LAYER == 1) ? g_h1h : g_h2h;
    __nv_bfloat16* Ol = (LAYER == 1) ? g_h1l : g_h2l;

    extern __shared__ char smem[];
    const uint32_t sb = smem_to_u32(smem);
    constexpr uint32_t A_HI = 0;
    constexpr uint32_t A_LO = 64 * LDSB;                   //  9216
    constexpr uint32_t B_HI = 2 * 64 * LDSB;               // 18432
    constexpr uint32_t B_LO = B_HI + BLK_N * LDSB;

    const int tid = threadIdx.x, warp = tid >> 5, lane = tid & 31;
    const int row0 = blockIdx.x * 64;
    const int nbase = blockIdx.y * BLK_N;
    const int wm = (warp & 3) * 16;
    const int wn = (warp >> 2) * WN;

    float acc[NT][4];
#pragma unroll
    for (int t = 0; t < NT; t++)
#pragma unroll
        for (int j = 0; j < 4; j++) acc[t][j] = 0.f;

    // ldmatrix address components (constant across chunks)
    const uint32_t a_off = (uint32_t)(wm + (lane & 15)) * LDSB + ((lane >> 4) * 16);
    const uint32_t b_off = (uint32_t)(wn + (lane & 7) + ((lane >> 4) << 3)) * LDSB
                           + (((lane >> 3) & 1) * 16);

    for (int kb = 0; kb < KB; kb++) {
        __syncthreads();
        // ---- load A chunk (64 x 64 bf16, hi+lo) ----
        {
            const size_t abase = (size_t)row0 * KPAD + kb * 64;
            for (int idx = tid; idx < 512; idx += 256) {
                int r = idx >> 3, g = idx & 7;
                const size_t src = abase + (size_t)r * KPAD + g * 8;
                char* dst = smem + r * LDSB + g * 16;
                *(uint4*)(dst + A_HI) = *(const uint4*)(Ah_g + src);
                *(uint4*)(dst + A_LO) = *(const uint4*)(Al_g + src);
            }
            const size_t bbase = (size_t)nbase * KPAD + kb * 64;
            for (int idx = tid; idx < BLK_N * 8; idx += 256) {
                int n = idx >> 3, g = idx & 7;
                const size_t src = bbase + (size_t)n * KPAD + g * 8;
                char* dst = smem + B_HI + n * LDSB + g * 16;
                *(uint4*)(dst) = *(const uint4*)(Bh_g + src);
                *(uint4*)(dst + (B_LO - B_HI)) = *(const uint4*)(Bl_g + src);
            }
        }
        __syncthreads();
        // ---- compute: 4 k16 steps ----
#pragma unroll
        for (int ks = 0; ks < 4; ks++) {
            uint32_t ah[4], al[4];
            ldsm4(ah, sb + A_HI + a_off + ks * 32);
            ldsm4(al, sb + A_LO + a_off + ks * 32);
#pragma unroll
            for (int t = 0; t < NT / 2; t++) {
                uint32_t bh[4], bl[4];
                const uint32_t boff = b_off + t * (16 * LDSB) + ks * 32;
                ldsm4(bh, sb + B_HI + boff);
                ldsm4(bl, sb + B_LO + boff);
                mma16816(acc[2 * t],     ah, bh);
                mma16816(acc[2 * t],     ah, bl);
                mma16816(acc[2 * t],     al, bh);
                mma16816(acc[2 * t + 1], ah, bh + 2);
                mma16816(acc[2 * t + 1], ah, bl + 2);
                mma16816(acc[2 * t + 1], al, bh + 2);
            }
        }
    }

    // ---- epilogue: bias + relu (+ split) ----
    const int r0 = row0 + wm + (lane >> 2);
    const int r1 = r0 + 8;
#pragma unroll
    for (int t = 0; t < NT; t++) {
        const int ncol = wn + t * 8 + (lane & 3) * 2;
        const float b0 = bias[nbase + ncol];
        const float b1 = bias[nbase + ncol + 1];
        float d0 = fmaxf(acc[t][0] + b0, 0.f);
        float d1 = fmaxf(acc[t][1] + b1, 0.f);
        float d2 = fmaxf(acc[t][2] + b0, 0.f);
        float d3 = fmaxf(acc[t][3] + b1, 0.f);
        if (SPLIT) {
            __nv_bfloat16 h0, l0, h1, l1;
            split_bf16(d0, h0, l0); split_bf16(d1, h1, l1);
            *(uint32_t*)(Oh + (size_t)r0 * OUTLD + nbase + ncol) = pack_bf16x2(h0, h1);
            *(uint32_t*)(Ol + (size_t)r0 * OUTLD + nbase + ncol) = pack_bf16x2(l0, l1);
            split_bf16(d2, h0, l0); split_bf16(d3, h1, l1);
            *(uint32_t*)(Oh + (size_t)r1 * OUTLD + nbase + ncol) = pack_bf16x2(h0, h1);
            *(uint32_t*)(Ol + (size_t)r1 * OUTLD + nbase + ncol) = pack_bf16x2(l0, l1);
        } else {
            *(float2*)(g_h3 + (size_t)r0 * OUTLD + nbase + ncol) = make_float2(d0, d1);
            *(float2*)(g_h3 + (size_t)r1 * OUTLD + nbase + ncol) = make_float2(d2, d3);
        }
    }
}

// ---------------- head ------------------------------------------------------
template <int RM, int U, bool RELU>
__device__ __forceinline__ void gemm_scalar(const float* __restrict__ As, int lda,
                                            const float* __restrict__ W,
                                            const float* __restrict__ bias,
                                            int N, int K,
                                            float* __restrict__ Cs, int ldc) {
    const int tc = threadIdx.x & 31;
    const int tr = threadIdx.x >> 5;
    const float* Arow = As + tr * RM * lda;
    float acc[RM][U];
#pragma unroll
    for (int i = 0; i < RM; i++)
#pragma unroll
        for (int u = 0; u < U; u++) acc[i][u] = 0.f;
    for (int k = 0; k < K; k++) {
        float wv[U];
        const float* Wk = W + (size_t)k * N + tc;
#pragma unroll
        for (int u = 0; u < U; u++) wv[u] = Wk[32 * u];
#pragma unroll
        for (int i = 0; i < RM; i++) {
            float xv = Arow[i * lda + k];
#pragma unroll
            for (int u = 0; u < U; u++) acc[i][u] += xv * wv[u];
        }
    }
#pragma unroll
    for (int u = 0; u < U; u++) {
        float b = bias[tc + 32 * u];
#pragma unroll
        for (int i = 0; i < RM; i++) {
            float v = acc[i][u] + b;
            if (RELU) v = fmaxf(v, 0.f);
            Cs[(tr * RM + i) * ldc + tc + 32 * u] = v;
        }
    }
}

__global__ __launch_bounds__(256)
void head_kernel(const float* __restrict__ Ws, const float* __restrict__ bs,
                 const float* __restrict__ Wc1, const float* __restrict__ bc1,
                 const float* __restrict__ Wc2, const float* __restrict__ bc2,
                 const float* __restrict__ Wc3, const float* __restrict__ bc3,
                 float* __restrict__ out) {
    extern __shared__ float sm[];
    float* comb = sm;              // 64 x 160
    float* c1s  = sm + 64 * 160;   // 64 x 64
    const int row0 = blockIdx.x * 64;

    for (int idx = threadIdx.x; idx < 64 * 32; idx += 256) {
        int r = idx >> 5, c4 = idx & 31;
        *(float4*)(comb + r * 160 + c4 * 4) =
            *(const float4*)(g_h3 + (size_t)(row0 + r) * 128 + c4 * 4);
    }
    for (int o = threadIdx.x; o < 64 * 32; o += 256) {
        int r = o >> 5, j = o & 31;
        const float* st = g_stats + (size_t)(row0 + r) * 8;
        float a = bs[j];
#pragma unroll
        for (int k = 0; k < 6; k++) a += st[k] * Ws[k * 32 + j];
        comb[r * 160 + 128 + j] = a;
    }
    __syncthreads();

    gemm_scalar<8, 2, true>(comb, 160, Wc1, bc1, 64, 160, c1s, 64);
    __syncthreads();
    gemm_scalar<8, 1, true>(c1s, 64, Wc2, bc2, 32, 64, comb, 32);
    __syncthreads();

    if (threadIdx.x < 64) {
        const float* cr = comb + threadIdx.x * 32;
        float z = bc3[0];
#pragma unroll
        for (int k = 0; k < 32; k++) z += cr[k] * Wc3[k];
        out[row0 + threadIdx.x] = 1.0f / (1.0f + expf(-z));
    }
}

// ---------------- launch ---------------------------------------------------
extern "C" void kernel_launch(void* const* d_in, const int* in_sizes, int n_in,
                              void* d_out, int out_size) {
    const float* x   = (const float*)d_in[0];
    const float* W1  = (const float*)d_in[1];
    const float* b1  = (const float*)d_in[2];
    const float* W2  = (const float*)d_in[3];
    const float* b2  = (const float*)d_in[4];
    const float* W3  = (const float*)d_in[5];
    const float* b3  = (const float*)d_in[6];
    const float* Ws  = (const float*)d_in[7];
    const float* bs  = (const float*)d_in[8];
    const float* Wc1 = (const float*)d_in[9];
    const float* bc1 = (const float*)d_in[10];
    const float* Wc2 = (const float*)d_in[11];
    const float* bc2 = (const float*)d_in[12];
    const float* Wc3 = (const float*)d_in[13];
    const float* bc3 = (const float*)d_in[14];
    float* out = (float*)d_out;

    const int SMEM_G12 = 2 * 64 * 144 + 2 * 256 * 144;   // 92160
    const int SMEM_G3  = 2 * 64 * 144 + 2 * 128 * 144;   // 55296
    const int SMEM_HEAD = (64 * 160 + 64 * 64) * 4;       // 57344

    static bool attr_set = false;
    if (!attr_set) {
        cudaFuncSetAttribute(gemm_hmma_kernel<1>,
                             cudaFuncAttributeMaxDynamicSharedMemorySize, SMEM_G12);
        cudaFuncSetAttribute(gemm_hmma_kernel<2>,
                             cudaFuncAttributeMaxDynamicSharedMemorySize, SMEM_G12);
        cudaFuncSetAttribute(gemm_hmma_kernel<3>,
                             cudaFuncAttributeMaxDynamicSharedMemorySize, SMEM_G3);
        cudaFuncSetAttribute(head_kernel,
                             cudaFuncAttributeMaxDynamicSharedMemorySize, SMEM_HEAD);
        attr_set = true;
    }

    prep_x_kernel<<<MTOT / 8, 256>>>(x);
    prep_w_kernel<<<(WT_TOTAL + 255) / 256, 256>>>(W1, W2, W3);

    dim3 g1(MTOT / 64, 2);   // N=512 in two 256 passes
    gemm_hmma_kernel<1><<<g1, 256, SMEM_G12>>>(b1);
    gemm_hmma_kernel<2><<<MTOT / 64, 256, SMEM_G12>>>(b2);
    gemm_hmma_kernel<3><<<MTOT / 64, 256, SMEM_G3>>>(b3);

    head_kernel<<<MTOT / 64, 256, SMEM_HEAD>>>(Ws, bs, Wc1, bc1, Wc2, bc2,
                                               Wc3, bc3, out);
}

// round 5
// speedup vs baseline: 4.2247x; 1.0736x over previous
#include <cuda_runtime.h>
#include <cuda_bf16.h>
#include <math.h>
#include <cstdint>

// ===========================================================================
// Fused MLP via mma.sync HMMA bf16 hi/lo split (fp32-grade accuracy):
//   prep_x : x fp32 -> x_hi/x_lo bf16 [65536,384] (+ row stats)
//   prep_w : W1/W2/W3 -> transposed [N,Kpad] bf16 hi/lo
//   gemm<L>: 512-thr CTA, tile M=128 x N=256 (128 for L3), warp tile 32x64
//            (32x32 L3), cp.async double-buffered K chunks of 64.
//   head   : stats@Ws -> concat -> C1,C2,C3 -> sigmoid
// ===========================================================================

#define MTOT 65536

// ---------------- device scratch -------------------------------------------
__device__ __nv_bfloat16 g_xh[(size_t)MTOT * 384];
__device__ __nv_bfloat16 g_xl[(size_t)MTOT * 384];
__device__ __nv_bfloat16 g_w1h[512 * 384], g_w1l[512 * 384];
__device__ __nv_bfloat16 g_w2h[256 * 512], g_w2l[256 * 512];
__device__ __nv_bfloat16 g_w3h[128 * 256], g_w3l[128 * 256];
__device__ __nv_bfloat16 g_h1h[(size_t)MTOT * 512], g_h1l[(size_t)MTOT * 512];
__device__ __nv_bfloat16 g_h2h[(size_t)MTOT * 256], g_h2l[(size_t)MTOT * 256];
__device__ float g_h3[(size_t)MTOT * 128];
__device__ float g_stats[(size_t)MTOT * 8];

// ---------------- helpers --------------------------------------------------
__device__ __forceinline__ uint32_t smem_to_u32(const void* p) {
    uint32_t a;
    asm("{ .reg .u64 t; cvta.to.shared.u64 t, %1; cvt.u32.u64 %0, t; }"
        : "=r"(a) : "l"(p));
    return a;
}
__device__ __forceinline__ void ldsm4(uint32_t* r, uint32_t addr) {
    asm volatile("ldmatrix.sync.aligned.m8n8.x4.shared.b16 {%0,%1,%2,%3}, [%4];"
        : "=r"(r[0]), "=r"(r[1]), "=r"(r[2]), "=r"(r[3]) : "r"(addr));
}
__device__ __forceinline__ void mma16816(float* c, const uint32_t* a,
                                         const uint32_t* b) {
    asm volatile(
        "mma.sync.aligned.m16n8k16.row.col.f32.bf16.bf16.f32 "
        "{%0,%1,%2,%3}, {%4,%5,%6,%7}, {%8,%9}, {%0,%1,%2,%3};"
        : "+f"(c[0]), "+f"(c[1]), "+f"(c[2]), "+f"(c[3])
        : "r"(a[0]), "r"(a[1]), "r"(a[2]), "r"(a[3]), "r"(b[0]), "r"(b[1]));
}
__device__ __forceinline__ void cp_async16(uint32_t dst, const void* src) {
    asm volatile("cp.async.cg.shared.global [%0], [%1], 16;"
        :: "r"(dst), "l"(src));
}
#define CP_COMMIT() asm volatile("cp.async.commit_group;" ::: "memory")
#define CP_WAIT(n)  asm volatile("cp.async.wait_group %0;" :: "n"(n) : "memory")

__device__ __forceinline__ void split_bf16(float v, __nv_bfloat16& hi,
                                           __nv_bfloat16& lo) {
    hi = __float2bfloat16(v);
    lo = __float2bfloat16(v - __bfloat162float(hi));
}
__device__ __forceinline__ uint32_t pack_bf16x2(__nv_bfloat16 a, __nv_bfloat16 b) {
    __nv_bfloat162 t; t.x = a; t.y = b;
    return *(uint32_t*)&t;
}

// ---------------- prep_x: split x + row stats ------------------------------
__global__ __launch_bounds__(256)
void prep_x_kernel(const float* __restrict__ x) {
    const int warp = threadIdx.x >> 5, lane = threadIdx.x & 31;
    const int r = blockIdx.x * 8 + warp;
    const float* xr = x + (size_t)r * 365;

    float v[12];
    float s = 0.f, mn = 3.4e38f, mx = -3.4e38f;
#pragma unroll
    for (int i = 0; i < 12; i++) {
        int k = lane + 32 * i;
        bool ok = k < 365;
        v[i] = ok ? xr[k] : 0.f;
        if (ok) { s += v[i]; mn = fminf(mn, v[i]); mx = fmaxf(mx, v[i]); }
    }
#pragma unroll
    for (int o = 16; o; o >>= 1) {
        s += __shfl_xor_sync(0xffffffffu, s, o);
        mn = fminf(mn, __shfl_xor_sync(0xffffffffu, mn, o));
        mx = fmaxf(mx, __shfl_xor_sync(0xffffffffu, mx, o));
    }
    const float mu = s * (1.0f / 365.0f);
    float s2 = 0.f, s3 = 0.f, s4 = 0.f;
#pragma unroll
    for (int i = 0; i < 12; i++) {
        int k = lane + 32 * i;
        if (k < 365) {
            float c = v[i] - mu, c2 = c * c;
            s2 += c2; s3 += c2 * c; s4 += c2 * c2;
        }
    }
#pragma unroll
    for (int o = 16; o; o >>= 1) {
        s2 += __shfl_xor_sync(0xffffffffu, s2, o);
        s3 += __shfl_xor_sync(0xffffffffu, s3, o);
        s4 += __shfl_xor_sync(0xffffffffu, s4, o);
    }
    if (lane == 0) {
        float var1 = s2 * (1.0f / 364.0f);
        float sig = sqrtf(var1);
        float m3 = s3 * (1.0f / 365.0f);
        float m4 = s4 * (1.0f / 365.0f);
        float sig2 = sig * sig;
        float* st = g_stats + (size_t)r * 8;
        st[0] = mu; st[1] = sig; st[2] = mn; st[3] = mx;
        st[4] = m3 / (sig * sig2 + 1e-8f);
        st[5] = m4 / (sig2 * sig2 + 1e-8f);
    }
#pragma unroll
    for (int i = 0; i < 12; i++) {
        int k = lane + 32 * i;
        float val = (k < 365) ? v[i] : 0.f;
        __nv_bfloat16 hi, lo;
        split_bf16(val, hi, lo);
        g_xh[(size_t)r * 384 + k] = hi;
        g_xl[(size_t)r * 384 + k] = lo;
    }
}

// ---------------- prep_w ----------------------------------------------------
#define W1T_ELEMS (512 * 384)
#define W2T_ELEMS (256 * 512)
#define W3T_ELEMS (128 * 256)
#define WT_TOTAL  (W1T_ELEMS + W2T_ELEMS + W3T_ELEMS)

__global__ __launch_bounds__(256)
void prep_w_kernel(const float* __restrict__ W1, const float* __restrict__ W2,
                   const float* __restrict__ W3) {
    int idx = blockIdx.x * 256 + threadIdx.x;
    if (idx >= WT_TOTAL) return;
    float v; __nv_bfloat16 hi, lo;
    if (idx < W1T_ELEMS) {
        int n = idx / 384, k = idx % 384;
        v = (k < 365) ? W1[(size_t)k * 512 + n] : 0.f;
        split_bf16(v, hi, lo);
        g_w1h[idx] = hi; g_w1l[idx] = lo;
    } else if (idx < W1T_ELEMS + W2T_ELEMS) {
        int j = idx - W1T_ELEMS;
        int n = j / 512, k = j % 512;
        v = W2[(size_t)k * 256 + n];
        split_bf16(v, hi, lo);
        g_w2h[j] = hi; g_w2l[j] = lo;
    } else {
        int j = idx - W1T_ELEMS - W2T_ELEMS;
        int n = j / 256, k = j % 256;
        v = W3[(size_t)k * 128 + n];
        split_bf16(v, hi, lo);
        g_w3h[j] = hi; g_w3l[j] = lo;
    }
}

// ---------------- HMMA GEMM, M=128 tile, cp.async double-buffered ----------
template <int LAYER>
__global__ __launch_bounds__(512, 1)
void gemm_hmma_kernel(const float* __restrict__ bias) {
    constexpr int KPAD  = (LAYER == 1) ? 384 : (LAYER == 2) ? 512 : 256;
    constexpr int BLK_N = (LAYER == 3) ? 128 : 256;
    constexpr int OUTLD = (LAYER == 1) ? 512 : (LAYER == 2) ? 256 : 128;
    constexpr int KB    = KPAD / 64;
    constexpr bool SPLIT = (LAYER != 3);
    constexpr int LDSB  = 144;               // 64 bf16 + 16B pad per smem row
    constexpr int WARP_N = BLK_N / 4;        // 64 or 32
    constexpr int NWT    = WARP_N / 16;      // n16 groups per warp: 4 or 2
    constexpr int NT     = 2 * NWT;          // n8 tiles per warp

    // per-buffer smem layout
    constexpr uint32_t A_HI = 0;
    constexpr uint32_t A_LO = 128 * LDSB;
    constexpr uint32_t B_HI = 2 * 128 * LDSB;
    constexpr uint32_t B_LO = B_HI + BLK_N * LDSB;
    constexpr uint32_t SBUF = B_LO + BLK_N * LDSB;   // bytes per buffer

    const __nv_bfloat16* Ah_g = (LAYER == 1) ? g_xh  : (LAYER == 2) ? g_h1h : g_h2h;
    const __nv_bfloat16* Al_g = (LAYER == 1) ? g_xl  : (LAYER == 2) ? g_h1l : g_h2l;
    const __nv_bfloat16* Bh_g = (LAYER == 1) ? g_w1h : (LAYER == 2) ? g_w2h : g_w3h;
    const __nv_bfloat16* Bl_g = (LAYER == 1) ? g_w1l : (LAYER == 2) ? g_w2l : g_w3l;
    __nv_bfloat16* Oh = (LAYER == 1) ? g_h1h : g_h2h;
    __nv_bfloat16* Ol = (LAYER == 1) ? g_h1l : g_h2l;

    extern __shared__ char smem[];
    const uint32_t sb = smem_to_u32(smem);

    const int tid = threadIdx.x, warp = tid >> 5, lane = tid & 31;
    const int row0 = blockIdx.x * 128;
    const int nbase = blockIdx.y * BLK_N;
    const int wm = (warp & 3) * 32;          // 4 M quarters of 32 rows
    const int wn = (warp >> 2) * WARP_N;     // 4 N quarters

    float acc[2][NT][4];
#pragma unroll
    for (int mt = 0; mt < 2; mt++)
#pragma unroll
        for (int t = 0; t < NT; t++)
#pragma unroll
            for (int j = 0; j < 4; j++) acc[mt][t][j] = 0.f;

    const uint32_t a_off = (uint32_t)(wm + (lane & 15)) * LDSB + ((lane >> 4) * 16);
    const uint32_t b_off = (uint32_t)(wn + (lane & 7) + ((lane >> 4) << 3)) * LDSB
                           + (((lane >> 3) & 1) * 16);

    // async chunk loader: chunk kb -> buffer buf
    auto load_chunk = [&](int kb, int buf) {
        const uint32_t bb = sb + (uint32_t)buf * SBUF;
        const size_t abase = (size_t)row0 * KPAD + kb * 64;
#pragma unroll
        for (int it = 0; it < 2; it++) {
            int idx = tid + it * 512;        // 1024 granules
            int r = idx >> 3, g = idx & 7;
            const size_t src = abase + (size_t)r * KPAD + g * 8;
            const uint32_t dst = bb + r * LDSB + g * 16;
            cp_async16(dst + A_HI, Ah_g + src);
            cp_async16(dst + A_LO, Al_g + src);
        }
        const size_t bbase = (size_t)nbase * KPAD + kb * 64;
#pragma unroll
        for (int it = 0; it < BLK_N / 64; it++) {
            int idx = tid + it * 512;        // BLK_N*8 granules
            int n = idx >> 3, g = idx & 7;
            const size_t src = bbase + (size_t)n * KPAD + g * 8;
            const uint32_t dst = bb + B_HI + n * LDSB + g * 16;
            cp_async16(dst, Bh_g + src);
            cp_async16(dst + (B_LO - B_HI), Bl_g + src);
        }
    };

    // prologue
    load_chunk(0, 0);
    CP_COMMIT();

    for (int kb = 0; kb < KB; kb++) {
        __syncthreads();                      // all warps done with buf (kb+1)&1
        if (kb + 1 < KB) {
            load_chunk(kb + 1, (kb + 1) & 1);
            CP_COMMIT();
            CP_WAIT(1);                       // chunk kb ready
        } else {
            CP_WAIT(0);
        }
        __syncthreads();

        const uint32_t bb = sb + (uint32_t)(kb & 1) * SBUF;
#pragma unroll
        for (int ks = 0; ks < 4; ks++) {
            uint32_t ah[2][4], al[2][4];
#pragma unroll
            for (int mt = 0; mt < 2; mt++) {
                const uint32_t ao = a_off + mt * (16 * LDSB) + ks * 32;
                ldsm4(ah[mt], bb + A_HI + ao);
                ldsm4(al[mt], bb + A_LO + ao);
            }
#pragma unroll
            for (int t = 0; t < NWT; t++) {
                uint32_t bh[4], bl[4];
                const uint32_t bo = b_off + t * (16 * LDSB) + ks * 32;
                ldsm4(bh, bb + B_HI + bo);
                ldsm4(bl, bb + B_LO + bo);
#pragma unroll
                for (int mt = 0; mt < 2; mt++) {
                    mma16816(acc[mt][2 * t],     ah[mt], bh);
                    mma16816(acc[mt][2 * t],     ah[mt], bl);
                    mma16816(acc[mt][2 * t],     al[mt], bh);
                    mma16816(acc[mt][2 * t + 1], ah[mt], bh + 2);
                    mma16816(acc[mt][2 * t + 1], ah[mt], bl + 2);
                    mma16816(acc[mt][2 * t + 1], al[mt], bh + 2);
                }
            }
        }
    }

    // ---- epilogue: bias + relu (+ split) ----
#pragma unroll
    for (int mt = 0; mt < 2; mt++) {
        const int r0 = row0 + wm + mt * 16 + (lane >> 2);
        const int r1 = r0 + 8;
#pragma unroll
        for (int t = 0; t < NT; t++) {
            const int ncol = wn + t * 8 + (lane & 3) * 2;
            const float b0 = bias[nbase + ncol];
            const float b1 = bias[nbase + ncol + 1];
            float d0 = fmaxf(acc[mt][t][0] + b0, 0.f);
            float d1 = fmaxf(acc[mt][t][1] + b1, 0.f);
            float d2 = fmaxf(acc[mt][t][2] + b0, 0.f);
            float d3 = fmaxf(acc[mt][t][3] + b1, 0.f);
            if (SPLIT) {
                __nv_bfloat16 h0, l0, h1, l1;
                split_bf16(d0, h0, l0); split_bf16(d1, h1, l1);
                *(uint32_t*)(Oh + (size_t)r0 * OUTLD + nbase + ncol) = pack_bf16x2(h0, h1);
                *(uint32_t*)(Ol + (size_t)r0 * OUTLD + nbase + ncol) = pack_bf16x2(l0, l1);
                split_bf16(d2, h0, l0); split_bf16(d3, h1, l1);
                *(uint32_t*)(Oh + (size_t)r1 * OUTLD + nbase + ncol) = pack_bf16x2(h0, h1);
                *(uint32_t*)(Ol + (size_t)r1 * OUTLD + nbase + ncol) = pack_bf16x2(l0, l1);
            } else {
                *(float2*)(g_h3 + (size_t)r0 * OUTLD + nbase + ncol) = make_float2(d0, d1);
                *(float2*)(g_h3 + (size_t)r1 * OUTLD + nbase + ncol) = make_float2(d2, d3);
            }
        }
    }
}

// ---------------- head ------------------------------------------------------
template <int RM, int U, bool RELU>
__device__ __forceinline__ void gemm_scalar(const float* __restrict__ As, int lda,
                                            const float* __restrict__ W,
                                            const float* __restrict__ bias,
                                            int N, int K,
                                            float* __restrict__ Cs, int ldc) {
    const int tc = threadIdx.x & 31;
    const int tr = threadIdx.x >> 5;
    const float* Arow = As + tr * RM * lda;
    float acc[RM][U];
#pragma unroll
    for (int i = 0; i < RM; i++)
#pragma unroll
        for (int u = 0; u < U; u++) acc[i][u] = 0.f;
    for (int k = 0; k < K; k++) {
        float wv[U];
        const float* Wk = W + (size_t)k * N + tc;
#pragma unroll
        for (int u = 0; u < U; u++) wv[u] = Wk[32 * u];
#pragma unroll
        for (int i = 0; i < RM; i++) {
            float xv = Arow[i * lda + k];
#pragma unroll
            for (int u = 0; u < U; u++) acc[i][u] += xv * wv[u];
        }
    }
#pragma unroll
    for (int u = 0; u < U; u++) {
        float b = bias[tc + 32 * u];
#pragma unroll
        for (int i = 0; i < RM; i++) {
            float v = acc[i][u] + b;
            if (RELU) v = fmaxf(v, 0.f);
            Cs[(tr * RM + i) * ldc + tc + 32 * u] = v;
        }
    }
}

__global__ __launch_bounds__(256)
void head_kernel(const float* __restrict__ Ws, const float* __restrict__ bs,
                 const float* __restrict__ Wc1, const float* __restrict__ bc1,
                 const float* __restrict__ Wc2, const float* __restrict__ bc2,
                 const float* __restrict__ Wc3, const float* __restrict__ bc3,
                 float* __restrict__ out) {
    extern __shared__ float sm[];
    float* comb = sm;              // 64 x 160
    float* c1s  = sm + 64 * 160;   // 64 x 64
    const int row0 = blockIdx.x * 64;

    for (int idx = threadIdx.x; idx < 64 * 32; idx += 256) {
        int r = idx >> 5, c4 = idx & 31;
        *(float4*)(comb + r * 160 + c4 * 4) =
            *(const float4*)(g_h3 + (size_t)(row0 + r) * 128 + c4 * 4);
    }
    for (int o = threadIdx.x; o < 64 * 32; o += 256) {
        int r = o >> 5, j = o & 31;
        const float* st = g_stats + (size_t)(row0 + r) * 8;
        float a = bs[j];
#pragma unroll
        for (int k = 0; k < 6; k++) a += st[k] * Ws[k * 32 + j];
        comb[r * 160 + 128 + j] = a;
    }
    __syncthreads();

    gemm_scalar<8, 2, true>(comb, 160, Wc1, bc1, 64, 160, c1s, 64);
    __syncthreads();
    gemm_scalar<8, 1, true>(c1s, 64, Wc2, bc2, 32, 64, comb, 32);
    __syncthreads();

    if (threadIdx.x < 64) {
        const float* cr = comb + threadIdx.x * 32;
        float z = bc3[0];
#pragma unroll
        for (int k = 0; k < 32; k++) z += cr[k] * Wc3[k];
        out[row0 + threadIdx.x] = 1.0f / (1.0f + expf(-z));
    }
}

// ---------------- launch ---------------------------------------------------
extern "C" void kernel_launch(void* const* d_in, const int* in_sizes, int n_in,
                              void* d_out, int out_size) {
    const float* x   = (const float*)d_in[0];
    const float* W1  = (const float*)d_in[1];
    const float* b1  = (const float*)d_in[2];
    const float* W2  = (const float*)d_in[3];
    const float* b2  = (const float*)d_in[4];
    const float* W3  = (const float*)d_in[5];
    const float* b3  = (const float*)d_in[6];
    const float* Ws  = (const float*)d_in[7];
    const float* bs  = (const float*)d_in[8];
    const float* Wc1 = (const float*)d_in[9];
    const float* bc1 = (const float*)d_in[10];
    const float* Wc2 = (const float*)d_in[11];
    const float* bc2 = (const float*)d_in[12];
    const float* Wc3 = (const float*)d_in[13];
    const float* bc3 = (const float*)d_in[14];
    float* out = (float*)d_out;

    // smem: (2*128 + 2*BLK_N) * 144 per buffer, x2 buffers
    const int SMEM_G12 = 2 * ((256 + 512) * 144);   // 221184
    const int SMEM_G3  = 2 * ((256 + 256) * 144);   // 147456
    const int SMEM_HEAD = (64 * 160 + 64 * 64) * 4;  // 57344

    static bool attr_set = false;
    if (!attr_set) {
        cudaFuncSetAttribute(gemm_hmma_kernel<1>,
                             cudaFuncAttributeMaxDynamicSharedMemorySize, SMEM_G12);
        cudaFuncSetAttribute(gemm_hmma_kernel<2>,
                             cudaFuncAttributeMaxDynamicSharedMemorySize, SMEM_G12);
        cudaFuncSetAttribute(gemm_hmma_kernel<3>,
                             cudaFuncAttributeMaxDynamicSharedMemorySize, SMEM_G3);
        cudaFuncSetAttribute(head_kernel,
                             cudaFuncAttributeMaxDynamicSharedMemorySize, SMEM_HEAD);
        attr_set = true;
    }

    prep_x_kernel<<<MTOT / 8, 256>>>(x);
    prep_w_kernel<<<(WT_TOTAL + 255) / 256, 256>>>(W1, W2, W3);

    dim3 g1(MTOT / 128, 2);   // N=512 in two 256-wide passes
    gemm_hmma_kernel<1><<<g1, 512, SMEM_G12>>>(b1);
    gemm_hmma_kernel<2><<<MTOT / 128, 512, SMEM_G12>>>(b2);
    gemm_hmma_kernel<3><<<MTOT / 128, 512, SMEM_G3>>>(b3);

    head_kernel<<<MTOT / 64, 256, SMEM_HEAD>>>(Ws, bs, Wc1, bc1, Wc2, bc2,
                                               Wc3, bc3, out);
}